// round 7
// baseline (speedup 1.0000x reference)
#include <cuda_runtime.h>
#include <math.h>

// Problem constants
constexpr int S   = 1024;   // tokens
constexpr int H   = 2048;   // hidden
constexpr int NH  = 16;     // q heads
constexpr int NKV = 4;      // kv heads
constexpr int D   = 128;    // head dim
constexpr int E   = 64;     // experts
constexpr int TK  = 8;      // top_k
constexpr int IM  = 768;    // moe intermediate
constexpr float EPS = 1e-6f;
constexpr int NA = S * TK;  // total assignments = 8192

// dense GEMM tiling
constexpr int KC  = 16;     // dense K-chunk
constexpr int AST = 20;     // dense A smem stride
constexpr int BST = 72;     // B smem stride (conflict-free: bank = 8k+n)

// MoE tiling (bandwidth-optimized)
constexpr int MKC  = 32;    // MoE K-chunk
constexpr int MAST = 36;    // MoE A smem stride (bank = 4r+c, conflict-free)
constexpr int NST  = 3;     // pipeline stages
constexpr int A_BUF = 128 * MAST;          // floats per A stage
constexpr int B_BUF = MKC * BST;           // floats per B stage
constexpr int GUP_SMEM = (NST * A_BUF + 2 * NST * B_BUF) * 4;  // bytes
constexpr int DWN_SMEM = (NST * A_BUF +     NST * B_BUF) * 4;

// ---------------- scratch (device globals; no allocation allowed) ----------
__device__ float g_xnorm [S * H];
__device__ float g_q     [S * NH * D];
__device__ float g_k     [S * NKV * D];
__device__ float g_v     [S * NKV * D];
__device__ float g_ctx   [S * NH * D];
__device__ float g_hid2  [S * H];
__device__ float g_hnorm [S * H];
__device__ int   g_topk_id[NA];
__device__ float g_topk_w [NA];
__device__ int   g_cnt   [E];
__device__ int   g_off   [E + 1];
__device__ int   g_cur   [E];
__device__ int   g_tok   [NA];     // expert-grouped token index
__device__ float g_ew    [NA];     // expert-grouped combine weight
__device__ int   g_pos   [NA];     // assignment a -> expert-grouped row
__device__ float g_act   [NA * IM];        // grouped weighted SwiGLU activations
__device__ float g_part  [(size_t)NA * H]; // grouped down-proj rows

__device__ __forceinline__ float* bufptr(int b) {
    switch (b) {
        case 0: return g_xnorm;
        case 4: return g_ctx;
        case 5: return g_hid2;
        case 6: return g_hnorm;
    }
    return nullptr;
}

// ---------------- helpers ----------------
__device__ __forceinline__ unsigned smaddr(const void* p) {
    return (unsigned)__cvta_generic_to_shared(p);
}
__device__ __forceinline__ unsigned cvt_tf32(float f) {
    unsigned u; asm("cvt.rna.tf32.f32 %0, %1;" : "=r"(u) : "f"(f)); return u;
}
__device__ __forceinline__ void cpa16(unsigned s, const void* g) {
    asm volatile("cp.async.cg.shared.global [%0], [%1], 16;" :: "r"(s), "l"(g));
}
__device__ __forceinline__ void cp_commit() { asm volatile("cp.async.commit_group;"); }
__device__ __forceinline__ void cp_wait0()  { asm volatile("cp.async.wait_group 0;"); }
__device__ __forceinline__ void cp_wait1()  { asm volatile("cp.async.wait_group 1;"); }
__device__ __forceinline__ void cp_wait2()  { asm volatile("cp.async.wait_group 2;"); }
__device__ __forceinline__ void mma_tf32(float c[4], const unsigned a[4], const unsigned b[2]) {
    asm volatile(
        "mma.sync.aligned.m16n8k8.row.col.f32.tf32.tf32.f32 "
        "{%0,%1,%2,%3}, {%4,%5,%6,%7}, {%8,%9}, {%0,%1,%2,%3};\n"
        : "+f"(c[0]), "+f"(c[1]), "+f"(c[2]), "+f"(c[3])
        : "r"(a[0]), "r"(a[1]), "r"(a[2]), "r"(a[3]), "r"(b[0]), "r"(b[1]));
}

// ---------------- RMSNorm ----------------
__global__ void rmsnorm_k(const float* __restrict__ x_ext, int xBuf,
                          const float* __restrict__ g, int outBuf) {
    const float* x = x_ext ? x_ext : bufptr(xBuf);
    float* out = bufptr(outBuf);
    int row = blockIdx.x, tid = threadIdx.x;
    const float* xr = x + (size_t)row * H;
    float ss = 0.f;
    for (int j = tid; j < H; j += 256) { float v = xr[j]; ss += v * v; }
    for (int o = 16; o; o >>= 1) ss += __shfl_xor_sync(0xffffffffu, ss, o);
    __shared__ float red[8];
    if ((tid & 31) == 0) red[tid >> 5] = ss;
    __syncthreads();
    if (tid < 32) {
        float v = (tid < 8) ? red[tid] : 0.f;
        for (int o = 4; o; o >>= 1) v += __shfl_xor_sync(0xffffffffu, v, o);
        if (tid == 0) red[0] = v;
    }
    __syncthreads();
    float inv = rsqrtf(red[0] / (float)H + EPS);
    for (int j = tid; j < H; j += 256) out[(size_t)row * H + j] = xr[j] * inv * g[j];
}

// ---------------- dense TF32 GEMM, cp.async double-buffered ----------------
// CTA tile 128x64, 8 warps (4m x 2n). mode 0: fused QKV (N=3072), mode 1: Wo.
__global__ __launch_bounds__(256) void dense_tf32(int aBuf,
        const float* __restrict__ W0, const float* __restrict__ W1,
        const float* __restrict__ W2, const float* __restrict__ res,
        int mode, int K) {
    const float* A = bufptr(aBuf);
    int m0 = blockIdx.y * 128;
    int n0c = blockIdx.x * 64;
    const float* B; int ldb, nb; float* Cp; int ldo;
    if (mode == 0) {
        if (n0c < 2048)      { B = W0; ldb = 2048; nb = n0c;        Cp = g_q; ldo = 2048; }
        else if (n0c < 2560) { B = W1; ldb = 512;  nb = n0c - 2048; Cp = g_k; ldo = 512; }
        else                 { B = W2; ldb = 512;  nb = n0c - 2560; Cp = g_v; ldo = 512; }
    } else { B = W0; ldb = 2048; nb = n0c; Cp = g_hid2; ldo = 2048; }
    __shared__ __align__(16) float As[2][128 * AST];
    __shared__ __align__(16) float Bs[2][KC * BST];
    int tid = threadIdx.x, lane = tid & 31, wid = tid >> 5;
    int wm = wid >> 1, wn = wid & 1;

    auto load_chunk = [&](int k0, int buf) {
        #pragma unroll
        for (int i = 0; i < 2; i++) {
            int id = tid + i * 256;
            int row = id >> 2, q = (id & 3) * 4;
            cpa16(smaddr(&As[buf][row * AST + q]),
                  A + (size_t)(m0 + row) * K + k0 + q);
        }
        int kr = tid >> 4, nq = (tid & 15) * 4;
        cpa16(smaddr(&Bs[buf][kr * BST + nq]),
              B + (size_t)(k0 + kr) * ldb + nb + nq);
        cp_commit();
    };

    float acc[2][4][4] = {};
    int NCH = K / KC;
    load_chunk(0, 0);
    for (int c = 0; c < NCH; c++) {
        int buf = c & 1;
        if (c + 1 < NCH) { load_chunk((c + 1) * KC, buf ^ 1); cp_wait1(); }
        else             { cp_wait0(); }
        __syncthreads();
        #pragma unroll
        for (int ks = 0; ks < 2; ks++) {
            int kk = ks * 8;
            unsigned Af[2][4];
            #pragma unroll
            for (int m = 0; m < 2; m++) {
                const float* ap = &As[buf][(wm * 32 + m * 16 + (lane >> 2)) * AST + kk + (lane & 3)];
                Af[m][0] = cvt_tf32(ap[0]);
                Af[m][1] = cvt_tf32(ap[8 * AST]);
                Af[m][2] = cvt_tf32(ap[4]);
                Af[m][3] = cvt_tf32(ap[8 * AST + 4]);
            }
            #pragma unroll
            for (int nt = 0; nt < 4; nt++) {
                const float* bp = &Bs[buf][(kk + (lane & 3)) * BST + wn * 32 + nt * 8 + (lane >> 2)];
                unsigned Bf[2] = { cvt_tf32(bp[0]), cvt_tf32(bp[4 * BST]) };
                #pragma unroll
                for (int m = 0; m < 2; m++) mma_tf32(acc[m][nt], Af[m], Bf);
            }
        }
        __syncthreads();
    }
    #pragma unroll
    for (int m = 0; m < 2; m++)
        #pragma unroll
        for (int nt = 0; nt < 4; nt++)
            #pragma unroll
            for (int r = 0; r < 4; r++) {
                int row = m0 + wm * 32 + m * 16 + (lane >> 2) + ((r >= 2) ? 8 : 0);
                int col = wn * 32 + nt * 8 + (lane & 3) * 2 + (r & 1);
                size_t oidx = (size_t)row * ldo + nb + col;
                float v = acc[m][nt][r];
                if (res) v += res[oidx];
                Cp[oidx] = v;
            }
}

// ---------------- causal flash attention (fp32) ----------------
__global__ __launch_bounds__(256) void attn_k() {
    constexpr int KT = 32;
    constexpr float SC = 0.0883883476483184f; // 1/sqrt(128)
    int qt = blockIdx.x, h = blockIdx.y;
    int kvh = h / (NH / NKV);
    int tid = threadIdx.x;
    int qi = tid >> 2, qr = tid & 3;
    int qrow = qt * 64 + qi;
    int d0 = qr * 32;
    __shared__ float Ks[KT][D];
    __shared__ float Vs[KT][D];
    float qreg[32], acc[32];
    #pragma unroll
    for (int d = 0; d < 32; d++) {
        qreg[d] = g_q[(size_t)qrow * (NH * D) + h * D + d0 + d] * SC;
        acc[d] = 0.f;
    }
    float m = -1e30f, l = 0.f;
    int ktiles = qt * 2 + 2;
    for (int kt = 0; kt < ktiles; kt++) {
        int kb = kt * KT;
        for (int idx = tid; idx < KT * D; idx += 256) {
            int r = idx >> 7, c = idx & 127;
            Ks[r][c] = g_k[(size_t)(kb + r) * (NKV * D) + kvh * D + c];
            Vs[r][c] = g_v[(size_t)(kb + r) * (NKV * D) + kvh * D + c];
        }
        __syncthreads();
        float sc[KT];
        #pragma unroll
        for (int j = 0; j < KT; j++) {
            float p = 0.f;
            #pragma unroll
            for (int d = 0; d < 32; d++) p += qreg[d] * Ks[j][d0 + d];
            p += __shfl_xor_sync(0xffffffffu, p, 1);
            p += __shfl_xor_sync(0xffffffffu, p, 2);
            sc[j] = (kb + j <= qrow) ? p : -1e30f;
        }
        float tm = m;
        #pragma unroll
        for (int j = 0; j < KT; j++) tm = fmaxf(tm, sc[j]);
        float corr = __expf(m - tm);
        m = tm;
        l *= corr;
        #pragma unroll
        for (int d = 0; d < 32; d++) acc[d] *= corr;
        #pragma unroll
        for (int j = 0; j < KT; j++) {
            float p = __expf(sc[j] - m);
            l += p;
            #pragma unroll
            for (int d = 0; d < 32; d++) acc[d] += p * Vs[j][d0 + d];
        }
        __syncthreads();
    }
    float inv = 1.f / l;
    #pragma unroll
    for (int d = 0; d < 32; d++)
        g_ctx[(size_t)qrow * (NH * D) + h * D + d0 + d] = acc[d] * inv;
}

// ---------------- router: logits, softmax-top8, counts ----------------
__global__ void zero_cnt_k() { if (threadIdx.x < E) g_cnt[threadIdx.x] = 0; }

__global__ void router_k(const float* __restrict__ Wg) {
    int t = blockIdx.x, tid = threadIdx.x;   // blockDim = 64
    __shared__ float sh[H];
    __shared__ float lg[E];
    for (int j = tid; j < H; j += 64) sh[j] = g_hnorm[(size_t)t * H + j];
    __syncthreads();
    float lo = 0.f;
    for (int j = 0; j < H; j++) lo += sh[j] * Wg[(size_t)j * E + tid];
    lg[tid] = lo;
    __syncthreads();
    if (tid == 0) {
        float tmp[E];
        for (int e = 0; e < E; e++) tmp[e] = lg[e];
        int   id[TK]; float w[TK];
        for (int k = 0; k < TK; k++) {
            int best = 0; float bv = tmp[0];
            for (int e = 1; e < E; e++) if (tmp[e] > bv) { bv = tmp[e]; best = e; }
            id[k] = best; w[k] = bv; tmp[best] = -1e30f;
        }
        float mx = w[0], s = 0.f;
        for (int k = 0; k < TK; k++) { w[k] = expf(w[k] - mx); s += w[k]; }
        float inv = 1.f / s;
        for (int k = 0; k < TK; k++) {
            g_topk_id[t * TK + k] = id[k];
            g_topk_w [t * TK + k] = w[k] * inv;
            atomicAdd(&g_cnt[id[k]], 1);
        }
    }
}

__global__ void offsets_k() {
    if (threadIdx.x == 0) {
        int run = 0;
        for (int e = 0; e < E; e++) { g_off[e] = run; g_cur[e] = run; run += g_cnt[e]; }
        g_off[E] = run;
    }
}

__global__ void scatter_k() {
    int a = blockIdx.x * blockDim.x + threadIdx.x;
    if (a < NA) {
        int e = g_topk_id[a];
        int pos = atomicAdd(&g_cur[e], 1);
        g_tok[pos] = a >> 3;
        g_ew [pos] = g_topk_w[a];
        g_pos[a]   = pos;
    }
}

// ---------------- MoE gate/up TF32 GEMM + SwiGLU, 3-stage pipeline ---------
// grid (IM/64, 8, E), block 256. CTA tile 128 x 64, K = H, KC = 32.
__global__ __launch_bounds__(256) void moe_gateup_tf32(const float* __restrict__ Wgate,
                                                       const float* __restrict__ Wup) {
    int e = blockIdx.z;
    int base = g_off[e], cnt = g_off[e + 1] - base;
    int t0 = blockIdx.y * 128;
    if (t0 >= cnt) return;
    int i0 = blockIdx.x * 64;
    extern __shared__ __align__(16) float dyn[];
    float* AsP = dyn;                       // NST * A_BUF
    float* BgP = AsP + NST * A_BUF;         // NST * B_BUF
    float* BuP = BgP + NST * B_BUF;         // NST * B_BUF
    __shared__ int   stok[128];
    __shared__ float swt[128];
    int tid = threadIdx.x, lane = tid & 31, wid = tid >> 5;
    int wm = wid >> 1, wn = wid & 1;
    if (tid < 128) {
        int r = t0 + tid;
        if (r < cnt) { stok[tid] = g_tok[base + r]; swt[tid] = g_ew[base + r]; }
        else         { stok[tid] = 0; swt[tid] = 0.f; }
    }
    __syncthreads();
    const float* WgE = Wgate + (size_t)e * H * IM;
    const float* WuE = Wup   + (size_t)e * H * IM;

    auto load_chunk = [&](int k0, int buf) {
        float* As = AsP + buf * A_BUF;
        #pragma unroll
        for (int i = 0; i < 4; i++) {
            int id = tid + i * 256;                 // 1024 float4s
            int row = id >> 3, q = (id & 7) * 4;
            cpa16(smaddr(&As[row * MAST + q]),
                  g_hnorm + (size_t)stok[row] * H + k0 + q);
        }
        float* Bg = BgP + buf * B_BUF;
        float* Bu = BuP + buf * B_BUF;
        #pragma unroll
        for (int i = 0; i < 2; i++) {
            int id = tid + i * 256;                 // 512 float4s each
            int kr = id >> 4, nq = (id & 15) * 4;
            cpa16(smaddr(&Bg[kr * BST + nq]), WgE + (size_t)(k0 + kr) * IM + i0 + nq);
            cpa16(smaddr(&Bu[kr * BST + nq]), WuE + (size_t)(k0 + kr) * IM + i0 + nq);
        }
        cp_commit();
    };

    float accg[2][4][4] = {};
    float accu[2][4][4] = {};
    constexpr int NCH = H / MKC;   // 64
    load_chunk(0, 0);
    load_chunk(MKC, 1);
    for (int c = 0; c < NCH; c++) {
        int buf = c % NST;
        if (c + 2 < NCH) { load_chunk((c + 2) * MKC, (c + 2) % NST); cp_wait2(); }
        else if (c + 1 < NCH) cp_wait1();
        else                  cp_wait0();
        __syncthreads();
        const float* As = AsP + buf * A_BUF;
        const float* Bg = BgP + buf * B_BUF;
        const float* Bu = BuP + buf * B_BUF;
        #pragma unroll
        for (int ks = 0; ks < 4; ks++) {
            int kk = ks * 8;
            unsigned Af[2][4];
            #pragma unroll
            for (int m = 0; m < 2; m++) {
                const float* ap = &As[(wm * 32 + m * 16 + (lane >> 2)) * MAST + kk + (lane & 3)];
                Af[m][0] = cvt_tf32(ap[0]);
                Af[m][1] = cvt_tf32(ap[8 * MAST]);
                Af[m][2] = cvt_tf32(ap[4]);
                Af[m][3] = cvt_tf32(ap[8 * MAST + 4]);
            }
            #pragma unroll
            for (int nt = 0; nt < 4; nt++) {
                int off = (kk + (lane & 3)) * BST + wn * 32 + nt * 8 + (lane >> 2);
                unsigned Gf[2] = { cvt_tf32(Bg[off]), cvt_tf32(Bg[off + 4 * BST]) };
                unsigned Uf[2] = { cvt_tf32(Bu[off]), cvt_tf32(Bu[off + 4 * BST]) };
                #pragma unroll
                for (int m = 0; m < 2; m++) {
                    mma_tf32(accg[m][nt], Af[m], Gf);
                    mma_tf32(accu[m][nt], Af[m], Uf);
                }
            }
        }
        __syncthreads();
    }
    #pragma unroll
    for (int m = 0; m < 2; m++)
        #pragma unroll
        for (int nt = 0; nt < 4; nt++)
            #pragma unroll
            for (int r = 0; r < 4; r++) {
                int row = wm * 32 + m * 16 + (lane >> 2) + ((r >= 2) ? 8 : 0);
                int col = wn * 32 + nt * 8 + (lane & 3) * 2 + (r & 1);
                int gr = t0 + row;
                if (gr < cnt) {
                    float gg = accg[m][nt][r], uu = accu[m][nt][r];
                    float a = (gg / (1.f + __expf(-gg))) * uu * swt[row];
                    g_act[(size_t)(base + gr) * IM + i0 + col] = a;
                }
            }
}

// ---------------- MoE down TF32 GEMM, 3-stage pipeline ---------------------
// grid (H/64, 8, E), block 256. CTA tile 128 x 64, K = IM, KC = 32.
__global__ __launch_bounds__(256) void moe_down_tf32(const float* __restrict__ Wdown) {
    int e = blockIdx.z;
    int base = g_off[e], cnt = g_off[e + 1] - base;
    int t0 = blockIdx.y * 128;
    if (t0 >= cnt) return;
    int h0 = blockIdx.x * 64;
    extern __shared__ __align__(16) float dyn[];
    float* AsP = dyn;
    float* BsP = AsP + NST * A_BUF;
    int tid = threadIdx.x, lane = tid & 31, wid = tid >> 5;
    int wm = wid >> 1, wn = wid & 1;
    const float* WdE = Wdown + (size_t)e * IM * H;

    auto load_chunk = [&](int k0, int buf) {
        float* As = AsP + buf * A_BUF;
        #pragma unroll
        for (int i = 0; i < 4; i++) {
            int id = tid + i * 256;
            int row = id >> 3, q = (id & 7) * 4;
            int gr = t0 + row; if (gr >= cnt) gr = cnt - 1;
            cpa16(smaddr(&As[row * MAST + q]),
                  g_act + (size_t)(base + gr) * IM + k0 + q);
        }
        float* Bs = BsP + buf * B_BUF;
        #pragma unroll
        for (int i = 0; i < 2; i++) {
            int id = tid + i * 256;
            int kr = id >> 4, nq = (id & 15) * 4;
            cpa16(smaddr(&Bs[kr * BST + nq]), WdE + (size_t)(k0 + kr) * H + h0 + nq);
        }
        cp_commit();
    };

    float acc[2][4][4] = {};
    constexpr int NCH = IM / MKC;  // 24
    load_chunk(0, 0);
    load_chunk(MKC, 1);
    for (int c = 0; c < NCH; c++) {
        int buf = c % NST;
        if (c + 2 < NCH) { load_chunk((c + 2) * MKC, (c + 2) % NST); cp_wait2(); }
        else if (c + 1 < NCH) cp_wait1();
        else                  cp_wait0();
        __syncthreads();
        const float* As = AsP + buf * A_BUF;
        const float* Bs = BsP + buf * B_BUF;
        #pragma unroll
        for (int ks = 0; ks < 4; ks++) {
            int kk = ks * 8;
            unsigned Af[2][4];
            #pragma unroll
            for (int m = 0; m < 2; m++) {
                const float* ap = &As[(wm * 32 + m * 16 + (lane >> 2)) * MAST + kk + (lane & 3)];
                Af[m][0] = cvt_tf32(ap[0]);
                Af[m][1] = cvt_tf32(ap[8 * MAST]);
                Af[m][2] = cvt_tf32(ap[4]);
                Af[m][3] = cvt_tf32(ap[8 * MAST + 4]);
            }
            #pragma unroll
            for (int nt = 0; nt < 4; nt++) {
                int off = (kk + (lane & 3)) * BST + wn * 32 + nt * 8 + (lane >> 2);
                unsigned Bf[2] = { cvt_tf32(Bs[off]), cvt_tf32(Bs[off + 4 * BST]) };
                #pragma unroll
                for (int m = 0; m < 2; m++) mma_tf32(acc[m][nt], Af[m], Bf);
            }
        }
        __syncthreads();
    }
    #pragma unroll
    for (int m = 0; m < 2; m++)
        #pragma unroll
        for (int nt = 0; nt < 4; nt++)
            #pragma unroll
            for (int r = 0; r < 4; r++) {
                int row = wm * 32 + m * 16 + (lane >> 2) + ((r >= 2) ? 8 : 0);
                int col = wn * 32 + nt * 8 + (lane & 3) * 2 + (r & 1);
                int gr = t0 + row;
                if (gr < cnt)
                    g_part[(size_t)(base + gr) * H + h0 + col] = acc[m][nt][r];
            }
}

// ---------------- finalize: residual + sum of 8 grouped partial rows -------
__global__ void finalize_k(float* __restrict__ out) {
    size_t idx = (size_t)blockIdx.x * 256 + threadIdx.x;   // S*H total
    int t = (int)(idx >> 11);
    int hc = (int)(idx & 2047);
    float v = g_hid2[idx];
    #pragma unroll
    for (int k = 0; k < TK; k++)
        v += g_part[(size_t)g_pos[t * TK + k] * H + hc];
    out[idx] = v;
}

// ---------------- launch ----------------
extern "C" void kernel_launch(void* const* d_in, const int* in_sizes, int n_in,
                              void* d_out, int out_size) {
    const float* hidden = (const float*)d_in[0];
    const float* ln1_g  = (const float*)d_in[1];
    const float* ln2_g  = (const float*)d_in[2];
    const float* Wq     = (const float*)d_in[3];
    const float* Wk     = (const float*)d_in[4];
    const float* Wv     = (const float*)d_in[5];
    const float* Wo     = (const float*)d_in[6];
    const float* Wg     = (const float*)d_in[7];
    const float* Wgate  = (const float*)d_in[8];
    const float* Wup    = (const float*)d_in[9];
    const float* Wdown  = (const float*)d_in[10];
    float* out = (float*)d_out;

    cudaFuncSetAttribute(moe_gateup_tf32, cudaFuncAttributeMaxDynamicSharedMemorySize, GUP_SMEM);
    cudaFuncSetAttribute(moe_down_tf32,   cudaFuncAttributeMaxDynamicSharedMemorySize, DWN_SMEM);

    // 1. input RMSNorm -> buf0 (xnorm)
    rmsnorm_k<<<S, 256>>>(hidden, -1, ln1_g, 0);
    // 2. fused QKV projection (TF32 MMA, cp.async pipelined)
    dense_tf32<<<dim3(48, S / 128), 256>>>(0, Wq, Wk, Wv, nullptr, 0, H);
    // 3. causal GQA attention -> ctx(4)
    attn_k<<<dim3(S / 64, NH), 256>>>();
    // 4. output projection + residual -> hid2(5)
    dense_tf32<<<dim3(32, S / 128), 256>>>(4, Wo, nullptr, nullptr, hidden, 1, NH * D);
    // 5. post-attn RMSNorm -> hnorm(6)
    rmsnorm_k<<<S, 256>>>(nullptr, 5, ln2_g, 6);
    // 6. router + dispatch
    zero_cnt_k<<<1, 64>>>();
    router_k<<<S, 64>>>(Wg);
    offsets_k<<<1, 1>>>();
    scatter_k<<<(NA + 255) / 256, 256>>>();
    // 7. expert gate/up + SwiGLU (3-stage cp.async pipeline)
    moe_gateup_tf32<<<dim3(IM / 64, 8, E), 256, GUP_SMEM>>>(Wgate, Wup);
    // 8. expert down-proj (3-stage cp.async pipeline)
    moe_down_tf32<<<dim3(H / 64, 8, E), 256, DWN_SMEM>>>(Wdown);
    // 9. residual + combine
    finalize_k<<<(S * H) / 256, 256>>>(out);
    (void)in_sizes; (void)n_in; (void)out_size;
}

// round 11
// speedup vs baseline: 1.0080x; 1.0080x over previous
#include <cuda_runtime.h>
#include <math.h>

// Problem constants
constexpr int S   = 1024;   // tokens
constexpr int H   = 2048;   // hidden
constexpr int NH  = 16;     // q heads
constexpr int NKV = 4;      // kv heads
constexpr int D   = 128;    // head dim
constexpr int E   = 64;     // experts
constexpr int TK  = 8;      // top_k
constexpr int IM  = 768;    // moe intermediate
constexpr float EPS = 1e-6f;
constexpr int NA = S * TK;  // total assignments = 8192

// GEMM tiling (shared by dense + MoE)
constexpr int KC  = 16;     // K-chunk
constexpr int AST = 20;     // A smem stride (floats)
constexpr int BST = 72;     // B smem stride (floats)

// ---------------- scratch (device globals; no allocation allowed) ----------
__device__ float g_xnorm [S * H];
__device__ float g_q     [S * NH * D];
__device__ float g_k     [S * NKV * D];
__device__ float g_v     [S * NKV * D];
__device__ float g_ctx   [S * NH * D];
__device__ float g_hid2  [S * H];
__device__ float g_hnorm [S * H];
__device__ int   g_topk_id[NA];
__device__ float g_topk_w [NA];
__device__ int   g_cnt   [E];
__device__ int   g_off   [E + 1];
__device__ int   g_cur   [E];
__device__ int   g_tok   [NA];     // expert-grouped token index
__device__ float g_ew    [NA];     // expert-grouped combine weight
__device__ int   g_pos   [NA];     // assignment a -> expert-grouped row
__device__ float g_gate  [NA * IM];        // raw gate GEMM output (grouped rows)
__device__ float g_up    [NA * IM];        // raw up GEMM output
__device__ float g_act   [NA * IM];        // weighted SwiGLU activations
__device__ float g_part  [(size_t)NA * H]; // grouped down-proj rows

__device__ __forceinline__ float* bufptr(int b) {
    switch (b) {
        case 0: return g_xnorm;
        case 4: return g_ctx;
        case 5: return g_hid2;
        case 6: return g_hnorm;
    }
    return nullptr;
}

// ---------------- helpers ----------------
__device__ __forceinline__ unsigned smaddr(const void* p) {
    return (unsigned)__cvta_generic_to_shared(p);
}
__device__ __forceinline__ unsigned cvt_tf32(float f) {
    unsigned u; asm("cvt.rna.tf32.f32 %0, %1;" : "=r"(u) : "f"(f)); return u;
}
__device__ __forceinline__ void cpa16(unsigned s, const void* g) {
    asm volatile("cp.async.ca.shared.global [%0], [%1], 16;" :: "r"(s), "l"(g));
}
__device__ __forceinline__ void cp_commit() { asm volatile("cp.async.commit_group;"); }
__device__ __forceinline__ void cp_wait0()  { asm volatile("cp.async.wait_group 0;"); }
__device__ __forceinline__ void cp_wait1()  { asm volatile("cp.async.wait_group 1;"); }
__device__ __forceinline__ void mma_tf32(float c[4], const unsigned a[4], const unsigned b[2]) {
    asm volatile(
        "mma.sync.aligned.m16n8k8.row.col.f32.tf32.tf32.f32 "
        "{%0,%1,%2,%3}, {%4,%5,%6,%7}, {%8,%9}, {%0,%1,%2,%3};\n"
        : "+f"(c[0]), "+f"(c[1]), "+f"(c[2]), "+f"(c[3])
        : "r"(a[0]), "r"(a[1]), "r"(a[2]), "r"(a[3]), "r"(b[0]), "r"(b[1]));
}

// ---------------- RMSNorm ----------------
__global__ void rmsnorm_k(const float* __restrict__ x_ext, int xBuf,
                          const float* __restrict__ g, int outBuf) {
    const float* x = x_ext ? x_ext : bufptr(xBuf);
    float* out = bufptr(outBuf);
    int row = blockIdx.x, tid = threadIdx.x;
    const float* xr = x + (size_t)row * H;
    float ss = 0.f;
    for (int j = tid; j < H; j += 256) { float v = xr[j]; ss += v * v; }
    for (int o = 16; o; o >>= 1) ss += __shfl_xor_sync(0xffffffffu, ss, o);
    __shared__ float red[8];
    if ((tid & 31) == 0) red[tid >> 5] = ss;
    __syncthreads();
    if (tid < 32) {
        float v = (tid < 8) ? red[tid] : 0.f;
        for (int o = 4; o; o >>= 1) v += __shfl_xor_sync(0xffffffffu, v, o);
        if (tid == 0) red[0] = v;
    }
    __syncthreads();
    float inv = rsqrtf(red[0] / (float)H + EPS);
    for (int j = tid; j < H; j += 256) out[(size_t)row * H + j] = xr[j] * inv * g[j];
}

// ---------------- dense TF32 GEMM, cp.async double-buffered ----------------
// CTA tile 128x64, 8 warps (4m x 2n). mode 0: fused QKV (N=3072), mode 1: Wo.
__global__ __launch_bounds__(256) void dense_tf32(int aBuf,
        const float* __restrict__ W0, const float* __restrict__ W1,
        const float* __restrict__ W2, const float* __restrict__ res,
        int mode, int K) {
    const float* A = bufptr(aBuf);
    int m0 = blockIdx.y * 128;
    int n0c = blockIdx.x * 64;
    const float* B; int ldb, nb; float* Cp; int ldo;
    if (mode == 0) {
        if (n0c < 2048)      { B = W0; ldb = 2048; nb = n0c;        Cp = g_q; ldo = 2048; }
        else if (n0c < 2560) { B = W1; ldb = 512;  nb = n0c - 2048; Cp = g_k; ldo = 512; }
        else                 { B = W2; ldb = 512;  nb = n0c - 2560; Cp = g_v; ldo = 512; }
    } else { B = W0; ldb = 2048; nb = n0c; Cp = g_hid2; ldo = 2048; }
    __shared__ __align__(16) float As[2][128 * AST];
    __shared__ __align__(16) float Bs[2][KC * BST];
    int tid = threadIdx.x, lane = tid & 31, wid = tid >> 5;
    int wm = wid >> 1, wn = wid & 1;

    auto load_chunk = [&](int k0, int buf) {
        #pragma unroll
        for (int i = 0; i < 2; i++) {
            int id = tid + i * 256;
            int row = id >> 2, q = (id & 3) * 4;
            cpa16(smaddr(&As[buf][row * AST + q]),
                  A + (size_t)(m0 + row) * K + k0 + q);
        }
        int kr = tid >> 4, nq = (tid & 15) * 4;
        cpa16(smaddr(&Bs[buf][kr * BST + nq]),
              B + (size_t)(k0 + kr) * ldb + nb + nq);
        cp_commit();
    };

    float acc[2][4][4] = {};
    int NCH = K / KC;
    load_chunk(0, 0);
    for (int c = 0; c < NCH; c++) {
        int buf = c & 1;
        if (c + 1 < NCH) { load_chunk((c + 1) * KC, buf ^ 1); cp_wait1(); }
        else             { cp_wait0(); }
        __syncthreads();
        #pragma unroll
        for (int ks = 0; ks < 2; ks++) {
            int kk = ks * 8;
            unsigned Af[2][4];
            #pragma unroll
            for (int m = 0; m < 2; m++) {
                const float* ap = &As[buf][(wm * 32 + m * 16 + (lane >> 2)) * AST + kk + (lane & 3)];
                Af[m][0] = cvt_tf32(ap[0]);
                Af[m][1] = cvt_tf32(ap[8 * AST]);
                Af[m][2] = cvt_tf32(ap[4]);
                Af[m][3] = cvt_tf32(ap[8 * AST + 4]);
            }
            #pragma unroll
            for (int nt = 0; nt < 4; nt++) {
                const float* bp = &Bs[buf][(kk + (lane & 3)) * BST + wn * 32 + nt * 8 + (lane >> 2)];
                unsigned Bf[2] = { cvt_tf32(bp[0]), cvt_tf32(bp[4 * BST]) };
                #pragma unroll
                for (int m = 0; m < 2; m++) mma_tf32(acc[m][nt], Af[m], Bf);
            }
        }
        __syncthreads();
    }
    #pragma unroll
    for (int m = 0; m < 2; m++)
        #pragma unroll
        for (int nt = 0; nt < 4; nt++)
            #pragma unroll
            for (int r = 0; r < 4; r++) {
                int row = m0 + wm * 32 + m * 16 + (lane >> 2) + ((r >= 2) ? 8 : 0);
                int col = wn * 32 + nt * 8 + (lane & 3) * 2 + (r & 1);
                size_t oidx = (size_t)row * ldo + nb + col;
                float v = acc[m][nt][r];
                if (res) v += res[oidx];
                Cp[oidx] = v;
            }
}

// ---------------- causal flash attention (fp32) ----------------
__global__ __launch_bounds__(256) void attn_k() {
    constexpr int KT = 32;
    constexpr float SC = 0.0883883476483184f; // 1/sqrt(128)
    int qt = blockIdx.x, h = blockIdx.y;
    int kvh = h / (NH / NKV);
    int tid = threadIdx.x;
    int qi = tid >> 2, qr = tid & 3;
    int qrow = qt * 64 + qi;
    int d0 = qr * 32;
    __shared__ float Ks[KT][D];
    __shared__ float Vs[KT][D];
    float qreg[32], acc[32];
    #pragma unroll
    for (int d = 0; d < 32; d++) {
        qreg[d] = g_q[(size_t)qrow * (NH * D) + h * D + d0 + d] * SC;
        acc[d] = 0.f;
    }
    float m = -1e30f, l = 0.f;
    int ktiles = qt * 2 + 2;
    for (int kt = 0; kt < ktiles; kt++) {
        int kb = kt * KT;
        for (int idx = tid; idx < KT * D; idx += 256) {
            int r = idx >> 7, c = idx & 127;
            Ks[r][c] = g_k[(size_t)(kb + r) * (NKV * D) + kvh * D + c];
            Vs[r][c] = g_v[(size_t)(kb + r) * (NKV * D) + kvh * D + c];
        }
        __syncthreads();
        float sc[KT];
        #pragma unroll
        for (int j = 0; j < KT; j++) {
            float p = 0.f;
            #pragma unroll
            for (int d = 0; d < 32; d++) p += qreg[d] * Ks[j][d0 + d];
            p += __shfl_xor_sync(0xffffffffu, p, 1);
            p += __shfl_xor_sync(0xffffffffu, p, 2);
            sc[j] = (kb + j <= qrow) ? p : -1e30f;
        }
        float tm = m;
        #pragma unroll
        for (int j = 0; j < KT; j++) tm = fmaxf(tm, sc[j]);
        float corr = __expf(m - tm);
        m = tm;
        l *= corr;
        #pragma unroll
        for (int d = 0; d < 32; d++) acc[d] *= corr;
        #pragma unroll
        for (int j = 0; j < KT; j++) {
            float p = __expf(sc[j] - m);
            l += p;
            #pragma unroll
            for (int d = 0; d < 32; d++) acc[d] += p * Vs[j][d0 + d];
        }
        __syncthreads();
    }
    float inv = 1.f / l;
    #pragma unroll
    for (int d = 0; d < 32; d++)
        g_ctx[(size_t)qrow * (NH * D) + h * D + d0 + d] = acc[d] * inv;
}

// ---------------- router: logits, softmax-top8, counts ----------------
__global__ void zero_cnt_k() { if (threadIdx.x < E) g_cnt[threadIdx.x] = 0; }

__global__ void router_k(const float* __restrict__ Wg) {
    int t = blockIdx.x, tid = threadIdx.x;   // blockDim = 64
    __shared__ float sh[H];
    __shared__ float lg[E];
    for (int j = tid; j < H; j += 64) sh[j] = g_hnorm[(size_t)t * H + j];
    __syncthreads();
    float lo = 0.f;
    for (int j = 0; j < H; j++) lo += sh[j] * Wg[(size_t)j * E + tid];
    lg[tid] = lo;
    __syncthreads();
    if (tid == 0) {
        float tmp[E];
        for (int e = 0; e < E; e++) tmp[e] = lg[e];
        int   id[TK]; float w[TK];
        for (int k = 0; k < TK; k++) {
            int best = 0; float bv = tmp[0];
            for (int e = 1; e < E; e++) if (tmp[e] > bv) { bv = tmp[e]; best = e; }
            id[k] = best; w[k] = bv; tmp[best] = -1e30f;
        }
        float mx = w[0], s = 0.f;
        for (int k = 0; k < TK; k++) { w[k] = expf(w[k] - mx); s += w[k]; }
        float inv = 1.f / s;
        for (int k = 0; k < TK; k++) {
            g_topk_id[t * TK + k] = id[k];
            g_topk_w [t * TK + k] = w[k] * inv;
            atomicAdd(&g_cnt[id[k]], 1);
        }
    }
}

__global__ void offsets_k() {
    if (threadIdx.x == 0) {
        int run = 0;
        for (int e = 0; e < E; e++) { g_off[e] = run; g_cur[e] = run; run += g_cnt[e]; }
        g_off[E] = run;
    }
}

__global__ void scatter_k() {
    int a = blockIdx.x * blockDim.x + threadIdx.x;
    if (a < NA) {
        int e = g_topk_id[a];
        int pos = atomicAdd(&g_cur[e], 1);
        g_tok[pos] = a >> 3;
        g_ew [pos] = g_topk_w[a];
        g_pos[a]   = pos;
    }
}

// ---------------- MoE gate/up GEMM (dense-shaped, single B stream) ---------
// grid (24, 8, E): x<12 -> gate n-tile x; x>=12 -> up n-tile x-12.
// CTA tile 128 x 64, KC=16, 2-stage. Writes RAW GEMM result (no activation).
__global__ __launch_bounds__(256) void moe_gu_tf32(const float* __restrict__ Wgate,
                                                   const float* __restrict__ Wup) {
    int e = blockIdx.z;
    int base = g_off[e], cnt = g_off[e + 1] - base;
    int t0 = blockIdx.y * 128;
    if (t0 >= cnt) return;
    int xx = blockIdx.x;
    const float* W; float* O;
    if (xx < 12) { W = Wgate + (size_t)e * H * IM; O = g_gate; }
    else         { W = Wup   + (size_t)e * H * IM; O = g_up; xx -= 12; }
    int i0 = xx * 64;
    __shared__ __align__(16) float As[2][128 * AST];
    __shared__ __align__(16) float Bs[2][KC * BST];
    __shared__ int stok[128];
    int tid = threadIdx.x, lane = tid & 31, wid = tid >> 5;
    int wm = wid >> 1, wn = wid & 1;
    if (tid < 128) {
        int r = t0 + tid;
        stok[tid] = (r < cnt) ? g_tok[base + r] : g_tok[base];
    }
    __syncthreads();

    auto load_chunk = [&](int k0, int buf) {
        #pragma unroll
        for (int i = 0; i < 2; i++) {
            int id = tid + i * 256;
            int row = id >> 2, q = (id & 3) * 4;
            cpa16(smaddr(&As[buf][row * AST + q]),
                  g_hnorm + (size_t)stok[row] * H + k0 + q);
        }
        int kr = tid >> 4, nq = (tid & 15) * 4;
        cpa16(smaddr(&Bs[buf][kr * BST + nq]),
              W + (size_t)(k0 + kr) * IM + i0 + nq);
        cp_commit();
    };

    float acc[2][4][4] = {};
    constexpr int NCH = H / KC;
    load_chunk(0, 0);
    for (int c = 0; c < NCH; c++) {
        int buf = c & 1;
        if (c + 1 < NCH) { load_chunk((c + 1) * KC, buf ^ 1); cp_wait1(); }
        else             { cp_wait0(); }
        __syncthreads();
        #pragma unroll
        for (int ks = 0; ks < 2; ks++) {
            int kk = ks * 8;
            unsigned Af[2][4];
            #pragma unroll
            for (int m = 0; m < 2; m++) {
                const float* ap = &As[buf][(wm * 32 + m * 16 + (lane >> 2)) * AST + kk + (lane & 3)];
                Af[m][0] = cvt_tf32(ap[0]);
                Af[m][1] = cvt_tf32(ap[8 * AST]);
                Af[m][2] = cvt_tf32(ap[4]);
                Af[m][3] = cvt_tf32(ap[8 * AST + 4]);
            }
            #pragma unroll
            for (int nt = 0; nt < 4; nt++) {
                const float* bp = &Bs[buf][(kk + (lane & 3)) * BST + wn * 32 + nt * 8 + (lane >> 2)];
                unsigned Bf[2] = { cvt_tf32(bp[0]), cvt_tf32(bp[4 * BST]) };
                #pragma unroll
                for (int m = 0; m < 2; m++) mma_tf32(acc[m][nt], Af[m], Bf);
            }
        }
        __syncthreads();
    }
    #pragma unroll
    for (int m = 0; m < 2; m++)
        #pragma unroll
        for (int nt = 0; nt < 4; nt++) {
            int rr = wm * 32 + m * 16 + (lane >> 2);
            int colb = wn * 32 + nt * 8 + (lane & 3) * 2;
            if (t0 + rr < cnt)
                *(float2*)&O[(size_t)(base + t0 + rr) * IM + i0 + colb] =
                    make_float2(acc[m][nt][0], acc[m][nt][1]);
            if (t0 + rr + 8 < cnt)
                *(float2*)&O[(size_t)(base + t0 + rr + 8) * IM + i0 + colb] =
                    make_float2(acc[m][nt][2], acc[m][nt][3]);
        }
}

// ---------------- SwiGLU + combine-weight elementwise ----------------------
// g_act[p][i] = silu(g_gate[p][i]) * g_up[p][i] * g_ew[p]
__global__ void swiglu_k() {
    int i4 = blockIdx.x * 256 + threadIdx.x;       // NA*IM/4 float4s
    int p = i4 / (IM / 4);
    float w = g_ew[p];
    float4 gg = ((const float4*)g_gate)[i4];
    float4 uu = ((const float4*)g_up)[i4];
    float4 r;
    r.x = (gg.x / (1.f + __expf(-gg.x))) * uu.x * w;
    r.y = (gg.y / (1.f + __expf(-gg.y))) * uu.y * w;
    r.z = (gg.z / (1.f + __expf(-gg.z))) * uu.z * w;
    r.w = (gg.w / (1.f + __expf(-gg.w))) * uu.w * w;
    ((float4*)g_act)[i4] = r;
}

// ---------------- MoE down GEMM (dense-shaped) -> grouped partial rows -----
// grid (32, 8, E). CTA tile 128 x 64, KC=16, 2-stage.
__global__ __launch_bounds__(256) void moe_down_tf32(const float* __restrict__ Wdown) {
    int e = blockIdx.z;
    int base = g_off[e], cnt = g_off[e + 1] - base;
    int t0 = blockIdx.y * 128;
    if (t0 >= cnt) return;
    int h0 = blockIdx.x * 64;
    __shared__ __align__(16) float As[2][128 * AST];
    __shared__ __align__(16) float Bs[2][KC * BST];
    int tid = threadIdx.x, lane = tid & 31, wid = tid >> 5;
    int wm = wid >> 1, wn = wid & 1;
    const float* WdE = Wdown + (size_t)e * IM * H;

    auto load_chunk = [&](int k0, int buf) {
        #pragma unroll
        for (int i = 0; i < 2; i++) {
            int id = tid + i * 256;
            int row = id >> 2, q = (id & 3) * 4;
            int gr = t0 + row; if (gr >= cnt) gr = cnt - 1;
            cpa16(smaddr(&As[buf][row * AST + q]),
                  g_act + (size_t)(base + gr) * IM + k0 + q);
        }
        int kr = tid >> 4, nq = (tid & 15) * 4;
        cpa16(smaddr(&Bs[buf][kr * BST + nq]),
              WdE + (size_t)(k0 + kr) * H + h0 + nq);
        cp_commit();
    };

    float acc[2][4][4] = {};
    constexpr int NCH = IM / KC;
    load_chunk(0, 0);
    for (int c = 0; c < NCH; c++) {
        int buf = c & 1;
        if (c + 1 < NCH) { load_chunk((c + 1) * KC, buf ^ 1); cp_wait1(); }
        else             { cp_wait0(); }
        __syncthreads();
        #pragma unroll
        for (int ks = 0; ks < 2; ks++) {
            int kk = ks * 8;
            unsigned Af[2][4];
            #pragma unroll
            for (int m = 0; m < 2; m++) {
                const float* ap = &As[buf][(wm * 32 + m * 16 + (lane >> 2)) * AST + kk + (lane & 3)];
                Af[m][0] = cvt_tf32(ap[0]);
                Af[m][1] = cvt_tf32(ap[8 * AST]);
                Af[m][2] = cvt_tf32(ap[4]);
                Af[m][3] = cvt_tf32(ap[8 * AST + 4]);
            }
            #pragma unroll
            for (int nt = 0; nt < 4; nt++) {
                const float* bp = &Bs[buf][(kk + (lane & 3)) * BST + wn * 32 + nt * 8 + (lane >> 2)];
                unsigned Bf[2] = { cvt_tf32(bp[0]), cvt_tf32(bp[4 * BST]) };
                #pragma unroll
                for (int m = 0; m < 2; m++) mma_tf32(acc[m][nt], Af[m], Bf);
            }
        }
        __syncthreads();
    }
    #pragma unroll
    for (int m = 0; m < 2; m++)
        #pragma unroll
        for (int nt = 0; nt < 4; nt++) {
            int rr = wm * 32 + m * 16 + (lane >> 2);
            int colb = wn * 32 + nt * 8 + (lane & 3) * 2;
            if (t0 + rr < cnt)
                *(float2*)&g_part[(size_t)(base + t0 + rr) * H + h0 + colb] =
                    make_float2(acc[m][nt][0], acc[m][nt][1]);
            if (t0 + rr + 8 < cnt)
                *(float2*)&g_part[(size_t)(base + t0 + rr + 8) * H + h0 + colb] =
                    make_float2(acc[m][nt][2], acc[m][nt][3]);
        }
}

// ---------------- finalize: residual + sum of 8 grouped partial rows -------
__global__ void finalize_k(float* __restrict__ out) {
    size_t idx = (size_t)blockIdx.x * 256 + threadIdx.x;   // S*H total
    int t = (int)(idx >> 11);
    int hc = (int)(idx & 2047);
    float v = g_hid2[idx];
    #pragma unroll
    for (int k = 0; k < TK; k++)
        v += g_part[(size_t)g_pos[t * TK + k] * H + hc];
    out[idx] = v;
}

// ---------------- launch ----------------
extern "C" void kernel_launch(void* const* d_in, const int* in_sizes, int n_in,
                              void* d_out, int out_size) {
    const float* hidden = (const float*)d_in[0];
    const float* ln1_g  = (const float*)d_in[1];
    const float* ln2_g  = (const float*)d_in[2];
    const float* Wq     = (const float*)d_in[3];
    const float* Wk     = (const float*)d_in[4];
    const float* Wv     = (const float*)d_in[5];
    const float* Wo     = (const float*)d_in[6];
    const float* Wg     = (const float*)d_in[7];
    const float* Wgate  = (const float*)d_in[8];
    const float* Wup    = (const float*)d_in[9];
    const float* Wdown  = (const float*)d_in[10];
    float* out = (float*)d_out;

    // 1. input RMSNorm -> buf0 (xnorm)
    rmsnorm_k<<<S, 256>>>(hidden, -1, ln1_g, 0);
    // 2. fused QKV projection
    dense_tf32<<<dim3(48, S / 128), 256>>>(0, Wq, Wk, Wv, nullptr, 0, H);
    // 3. causal GQA attention -> ctx(4)
    attn_k<<<dim3(S / 64, NH), 256>>>();
    // 4. output projection + residual -> hid2(5)
    dense_tf32<<<dim3(32, S / 128), 256>>>(4, Wo, nullptr, nullptr, hidden, 1, NH * D);
    // 5. post-attn RMSNorm -> hnorm(6)
    rmsnorm_k<<<S, 256>>>(nullptr, 5, ln2_g, 6);
    // 6. router + dispatch
    zero_cnt_k<<<1, 64>>>();
    router_k<<<S, 64>>>(Wg);
    offsets_k<<<1, 1>>>();
    scatter_k<<<(NA + 255) / 256, 256>>>();
    // 7. expert gate + up GEMMs (dense-shaped CTAs)
    moe_gu_tf32<<<dim3(24, 8, E), 256>>>(Wgate, Wup);
    // 8. SwiGLU + combine weight
    swiglu_k<<<NA * IM / 4 / 256, 256>>>();
    // 9. expert down-proj
    moe_down_tf32<<<dim3(32, 8, E), 256>>>(Wdown);
    // 10. residual + combine
    finalize_k<<<(S * H) / 256, 256>>>(out);
    (void)in_sizes; (void)n_in; (void)out_size;
}